// round 9
// baseline (speedup 1.0000x reference)
#include <cuda_runtime.h>
#include <cuda_fp16.h>
#include <mma.h>
#include <math.h>
#include <stdint.h>

using namespace nvcuda;

#define DD 300
#define NCOLS 1800
#define KK2 320             // K padded to 320 (zero-padded)
#define MAXN 50000
#define MAXE 250000
#define MPAD 50048          // 391 * 128
#define STAGES 4
#define KT 32
#define NT (KK2 / KT)       // 10
#define SFST 608            // d_Sf row stride (floats): Q[0..300), Cd[304..604)
#define SHST 960            // d_Sh row stride (halves): K[0..300), V[320..620), Cs[640..940)

// ---- static scratch (allocation-free rule: __device__ globals) ----
__device__ __half d_Ah[(size_t)MPAD * KK2];    // [MPAD][320] fp16, pads stay 0
__device__ __half d_WhT[(size_t)1920 * KK2];   // [1920][320] Wbig^T fp16
__device__ float  d_Sf[(size_t)MPAD * SFST];   // fp32: Q | Cd
__device__ __half d_Sh[(size_t)MPAD * SHST];   // fp16: K | V | Cs
__device__ float  d_NLi[3 * DD];
__device__ float  d_NLj[3 * DD];
__device__ float  d_W2f[2 * DD];
__device__ float  d_c0[DD];
__device__ float  d_T8[8 * DD];
__device__ float  d_G8[8 * DD];
// CSR scratch
__device__ int  d_deg[MAXN];
__device__ int  d_rowptr[MAXN + 1];
__device__ int  d_cursor[MAXN];
__device__ int  d_blksum[256];
__device__ int2 d_edges[MAXE];

__device__ __forceinline__ float fast_tanh(float x) {
    float r;
    asm("tanh.approx.f32 %0, %1;" : "=f"(r) : "f"(x));
    return r;
}
__device__ __forceinline__ float4 h4tof4(uint2 u) {
    __half2 a = *(__half2*)&u.x, b = *(__half2*)&u.y;
    float2 fa = __half22float2(a), fb = __half22float2(b);
    return make_float4(fa.x, fa.y, fb.x, fb.y);
}

// ---------------- fold 1 ----------------
__global__ void fold1_kernel(const float* __restrict__ Wn, const float* __restrict__ Wxy,
                             const float* __restrict__ Wloc, const float* __restrict__ Wfus,
                             const float* __restrict__ vocab, const float* __restrict__ bxy,
                             const float* __restrict__ bn, const float* __restrict__ bobj,
                             const float* __restrict__ bloc, const float* __restrict__ bfus) {
    int c = blockIdx.x * blockDim.x + threadIdx.x;
    if (c >= DD) return;
    float nli0 = 0, nli1 = 0, nli2 = 0, nlj0 = 0, nlj1 = 0, nlj2 = 0;
    float w20 = 0, w21 = 0, c0 = 0;
    float t0 = 0, t1 = 0, t2 = 0, t3 = 0, t4 = 0, t5 = 0, t6 = 0;
    for (int k = 0; k < DD; k++) {
        float wl0 = Wloc[k * DD + c];
        float wl1 = Wloc[(DD + k) * DD + c];
        float wl2 = Wloc[(2 * DD + k) * DD + c];
        float wn0 = Wn[k], wn1 = Wn[DD + k], wn2 = Wn[2 * DD + k];
        nli0 = fmaf(wn0, wl1, nli0); nli1 = fmaf(wn1, wl1, nli1); nli2 = fmaf(wn2, wl1, nli2);
        nlj0 = fmaf(wn0, wl2, nlj0); nlj1 = fmaf(wn1, wl2, nlj1); nlj2 = fmaf(wn2, wl2, nlj2);
        w20 = fmaf(Wxy[k], wl0, w20); w21 = fmaf(Wxy[DD + k], wl0, w21);
        c0 = fmaf(bxy[k], wl0, c0);
        c0 = fmaf(bn[k], wl1 + wl2, c0);
        float wf0 = Wfus[k * DD + c];
        float wf1 = Wfus[(DD + k) * DD + c];
        t0 = fmaf(vocab[2 * DD + k], wf1, t0);
        t1 = fmaf(vocab[3 * DD + k], wf1, t1);
        t2 = fmaf(vocab[4 * DD + k], wf1, t2);
        t3 = fmaf(vocab[5 * DD + k], wf1, t3);
        t4 = fmaf(vocab[6 * DD + k], wf1, t4);
        t5 = fmaf(vocab[k], wf0, t5);
        t6 = fmaf(vocab[DD + k], wf0, t6);
    }
    d_NLi[0 * DD + c] = nli0; d_NLi[1 * DD + c] = nli1; d_NLi[2 * DD + c] = nli2;
    d_NLj[0 * DD + c] = nlj0; d_NLj[1 * DD + c] = nlj1; d_NLj[2 * DD + c] = nlj2;
    d_W2f[c] = w20; d_W2f[DD + c] = w21;
    d_c0[c] = c0 + bobj[c] + bloc[c];
    d_T8[0 * DD + c] = t0; d_T8[1 * DD + c] = t1; d_T8[2 * DD + c] = t2;
    d_T8[3 * DD + c] = t3; d_T8[4 * DD + c] = t4; d_T8[5 * DD + c] = t5;
    d_T8[6 * DD + c] = t6; d_T8[7 * DD + c] = bfus[c];
}

// ---------------- fold 2: G8 = T8 @ We ----------------
__global__ void fold2_kernel(const float* __restrict__ We) {
    int c = blockIdx.x * blockDim.x + threadIdx.x;
    if (c >= DD) return;
    float g[8] = {0, 0, 0, 0, 0, 0, 0, 0};
    for (int k = 0; k < DD; k++) {
        float w = We[k * DD + c];
        #pragma unroll
        for (int j = 0; j < 8; j++) g[j] = fmaf(d_T8[j * DD + k], w, g[j]);
    }
    #pragma unroll
    for (int j = 0; j < 8; j++) d_G8[j * DD + c] = g[j];
}

// ---------------- build A (fp16; pad entries never written, stay zero) ----------------
__global__ void buildA_kernel(const float* __restrict__ x, const float* __restrict__ nrm, int Nn) {
    int idx = blockIdx.x * blockDim.x + threadIdx.x;
    if (idx >= Nn * 304) return;
    int n = idx / 304, k = idx - n * 304;
    float v;
    if (k < DD) v = x[n * DD + k];
    else if (k < DD + 3) v = nrm[n * 3 + (k - DD)];
    else v = 1.0f;
    d_Ah[(size_t)n * KK2 + k] = __float2half_rn(v);
}

// ---------------- build WhT [c][k] fp16 ----------------
__global__ void buildW_kernel(const float* __restrict__ Wq, const float* __restrict__ Wk,
                              const float* __restrict__ Wv, const float* __restrict__ Wskip,
                              const float* __restrict__ Wobj, const float* __restrict__ bq,
                              const float* __restrict__ bk, const float* __restrict__ bv,
                              const float* __restrict__ bskip) {
    int idx = blockIdx.x * blockDim.x + threadIdx.x;
    if (idx >= NCOLS * 304) return;
    int c = idx / 304, k = idx - c * 304;
    int b = c / DD, cc = c - b * DD;
    float v = 0.0f;
    if (k < DD) {
        if (b == 0) v = Wq[k * DD + cc];
        else if (b == 1) v = Wk[k * DD + cc];
        else if (b == 2) v = Wv[k * DD + cc];
        else if (b == 3) v = Wskip[k * DD + cc];
        else if (b == 4) v = Wobj[k * DD + cc] - Wobj[(DD + k) * DD + cc];
        else v = Wobj[(DD + k) * DD + cc];
    } else if (k < DD + 3) {
        int r = k - DD;
        if (b == 4) v = d_NLi[r * DD + cc];
        else if (b == 5) v = d_NLj[r * DD + cc];
    } else {
        if (b == 0) v = bq[cc];
        else if (b == 1) v = bk[cc];
        else if (b == 2) v = bv[cc];
        else if (b == 3) v = bskip[cc];
        else if (b == 4) v = d_c0[cc];
    }
    d_WhT[(size_t)c * KK2 + k] = __float2half_rn(v);
}

// ---------------- node GEMM (fp16 wmma m16n16k16, cp.async 4-stage, routed epilogue) ----
__global__ void __launch_bounds__(256, 2) gemm_fp16_kernel(float* __restrict__ out, int Nn) {
    extern __shared__ __half sm[];
    __half (*As)[128][40] = (__half (*)[128][40])sm;                         // STAGES x 128 x 40
    __half (*Bs)[128][40] = (__half (*)[128][40])(sm + STAGES * 128 * 40);   // STAGES x 128 x 40
    float (*stage)[132] = (float (*)[132])sm;                                // epilogue reuse

    int tid = threadIdx.x;
    int wid = tid >> 5;
    int wm = wid >> 2;            // 0..1
    int wn = wid & 3;             // 0..3
    int row0 = blockIdx.y * 128, col0 = blockIdx.x * 128;

    wmma::fragment<wmma::accumulator, 16, 16, 16, float> acc[4][2];
    #pragma unroll
    for (int i = 0; i < 4; i++)
        #pragma unroll
        for (int j = 0; j < 2; j++) wmma::fill_fragment(acc[i][j], 0.0f);

    auto loadStage = [&](int st, int kt) {
        #pragma unroll
        for (int u = 0; u < 2; u++) {
            int idx = tid + 256 * u;       // 0..511
            int row = idx >> 2, seg = idx & 3;
            const __half* ga = &d_Ah[(size_t)(row0 + row) * KK2 + kt + seg * 8];
            uint32_t da = (uint32_t)__cvta_generic_to_shared(&As[st][row][seg * 8]);
            asm volatile("cp.async.cg.shared.global [%0], [%1], 16;" :: "r"(da), "l"(ga));
            const __half* gb = &d_WhT[(size_t)(col0 + row) * KK2 + kt + seg * 8];
            uint32_t db = (uint32_t)__cvta_generic_to_shared(&Bs[st][row][seg * 8]);
            asm volatile("cp.async.cg.shared.global [%0], [%1], 16;" :: "r"(db), "l"(gb));
        }
    };

    #pragma unroll
    for (int i = 0; i < STAGES - 1; i++) {
        loadStage(i, i * KT);
        asm volatile("cp.async.commit_group;");
    }

    for (int s = 0; s < NT; s++) {
        asm volatile("cp.async.wait_group %0;" :: "n"(STAGES - 2));
        __syncthreads();
        int ld = s + STAGES - 1;
        if (ld < NT) loadStage(ld & (STAGES - 1), ld * KT);
        asm volatile("cp.async.commit_group;");

        int st = s & (STAGES - 1);
        #pragma unroll
        for (int ks = 0; ks < 2; ks++) {
            int k0 = ks * 16;
            wmma::fragment<wmma::matrix_b, 16, 16, 16, __half, wmma::col_major> bf[2];
            #pragma unroll
            for (int j = 0; j < 2; j++)
                wmma::load_matrix_sync(bf[j], &Bs[st][wn * 32 + j * 16][k0], 40);
            #pragma unroll
            for (int i = 0; i < 4; i++) {
                wmma::fragment<wmma::matrix_a, 16, 16, 16, __half, wmma::row_major> af;
                wmma::load_matrix_sync(af, &As[st][wm * 64 + i * 16][k0], 40);
                #pragma unroll
                for (int j = 0; j < 2; j++)
                    wmma::mma_sync(acc[i][j], af, bf[j], acc[i][j]);
            }
        }
    }

    // ---- routed epilogue: stage in smem, then write per logical block ----
    asm volatile("cp.async.wait_group 0;");
    __syncthreads();
    #pragma unroll
    for (int i = 0; i < 4; i++)
        #pragma unroll
        for (int j = 0; j < 2; j++)
            wmma::store_matrix_sync(&stage[wm * 64 + i * 16][wn * 32 + j * 16],
                                    acc[i][j], 132, wmma::mem_row_major);
    __syncthreads();

    #pragma unroll
    for (int it = 0; it < 16; it++) {
        int idx = tid + it * 256;          // 0..4095
        int r = idx >> 5;
        int c4 = (idx & 31) * 4;
        int gc = col0 + c4;
        if (gc >= NCOLS) continue;
        int n = row0 + r;
        float4 v = *(float4*)&stage[r][c4];
        int b = gc / DD;
        int cc = gc - b * DD;
        if (b == 0) {
            *(float4*)&d_Sf[(size_t)n * SFST + cc] = v;
        } else if (b == 4) {
            *(float4*)&d_Sf[(size_t)n * SFST + 304 + cc] = v;
        } else if (b == 3) {
            if (n < Nn) *(float4*)&out[(size_t)n * DD + cc] = v;
        } else {
            int off = (b == 1) ? 0 : (b == 2 ? 320 : 640);   // K, V, Cs
            __half2 h0 = __floats2half2_rn(v.x, v.y);
            __half2 h1 = __floats2half2_rn(v.z, v.w);
            uint2 u = make_uint2(*(uint32_t*)&h0, *(uint32_t*)&h1);
            *(uint2*)&d_Sh[(size_t)n * SHST + off + cc] = u;
        }
    }
}

// ---------------- CSR build ----------------
__global__ void zerodeg_kernel(int Nn) {
    int i = blockIdx.x * blockDim.x + threadIdx.x;
    if (i < Nn) d_deg[i] = 0;
}
__global__ void hist_kernel(const int* __restrict__ EI, int Ee) {
    int e = blockIdx.x * blockDim.x + threadIdx.x;
    if (e < Ee) atomicAdd(&d_deg[EI[Ee + e]], 1);
}
__global__ void scan1_kernel(int Nn) {
    __shared__ int sdata[256];
    int t = threadIdx.x;
    int i = blockIdx.x * 256 + t;
    int v = (i < Nn) ? d_deg[i] : 0;
    sdata[t] = v;
    __syncthreads();
    #pragma unroll
    for (int off = 1; off < 256; off <<= 1) {
        int x = (t >= off) ? sdata[t - off] : 0;
        __syncthreads();
        sdata[t] += x;
        __syncthreads();
    }
    if (i < Nn) d_rowptr[i] = sdata[t] - v;
    if (t == 255) d_blksum[blockIdx.x] = sdata[255];
}
__global__ void scan2_kernel(int NB) {
    __shared__ int sdata[256];
    int t = threadIdx.x;
    int v = (t < NB) ? d_blksum[t] : 0;
    sdata[t] = v;
    __syncthreads();
    #pragma unroll
    for (int off = 1; off < 256; off <<= 1) {
        int x = (t >= off) ? sdata[t - off] : 0;
        __syncthreads();
        sdata[t] += x;
        __syncthreads();
    }
    if (t < NB) d_blksum[t] = sdata[t] - v;
}
__global__ void scan3_kernel(int Nn) {
    int i = blockIdx.x * blockDim.x + threadIdx.x;
    if (i >= Nn) return;
    int val = d_rowptr[i] + d_blksum[i >> 8];
    d_rowptr[i] = val;
    d_cursor[i] = val;
    if (i == Nn - 1) d_rowptr[Nn] = val + d_deg[i];
}
__global__ void scatter_kernel(const int* __restrict__ EI, int Ee) {
    int e = blockIdx.x * blockDim.x + threadIdx.x;
    if (e >= Ee) return;
    int dst = EI[Ee + e];
    int pos = atomicAdd(&d_cursor[dst], 1);
    d_edges[pos] = make_int2(EI[e], e);
}

// ---------------- fused edge kernel with software pipelining ----------------
__global__ void __launch_bounds__(256) edgeF_kernel(const float* __restrict__ EA,
                                                    const float* __restrict__ Wcls,
                                                    const float* __restrict__ bcls,
                                                    float* __restrict__ out, int Nn) {
    __shared__ float sWcls[DD * 5];
    __shared__ float sG[8 * DD];
    __shared__ float sW2[2 * DD];
    __shared__ float sBcls[5];
    for (int i = threadIdx.x; i < DD * 5; i += 256) sWcls[i] = Wcls[i];
    for (int i = threadIdx.x; i < 8 * DD; i += 256) sG[i] = d_G8[i];
    for (int i = threadIdx.x; i < 2 * DD; i += 256) sW2[i] = d_W2f[i];
    if (threadIdx.x < 5) sBcls[threadIdx.x] = bcls[threadIdx.x];
    __syncthreads();

    int lane = threadIdx.x & 31;
    int n = blockIdx.x * 8 + (threadIdx.x >> 5);
    if (n >= Nn) return;

    int beg = d_rowptr[n], end = d_rowptr[n + 1];
    const float* rowQ = d_Sf + (size_t)n * SFST;

    float4 q[3], cd[3], acc[3];
    #pragma unroll
    for (int j = 0; j < 3; j++) {
        int ch = lane + 32 * j;
        if (ch < 75) {
            q[j]  = __ldg((const float4*)&rowQ[4 * ch]);
            cd[j] = __ldg((const float4*)&rowQ[304 + 4 * ch]);
        } else {
            q[j] = make_float4(0, 0, 0, 0);
            cd[j] = make_float4(0, 0, 0, 0);
        }
        acc[j] = make_float4(0, 0, 0, 0);
    }
    float den0 = 0, den1 = 0, den2 = 0, den3 = 0;

    // prefetch registers for next edge
    uint2 pk[3], pv[3], pcs[3];
    float4 pea = make_float4(0, 0, 0, 0);

    auto prefetch = [&](int p) {
        int2 se = __ldg(&d_edges[p]);
        const __half* rowS = d_Sh + (size_t)se.x * SHST;
        pea = __ldg((const float4*)&EA[4 * se.y]);
        #pragma unroll
        for (int j = 0; j < 3; j++) {
            int ch = lane + 32 * j;
            if (ch < 75) {
                pk[j]  = __ldg((const uint2*)(rowS + 4 * ch));
                pv[j]  = __ldg((const uint2*)(rowS + 320 + 4 * ch));
                pcs[j] = __ldg((const uint2*)(rowS + 640 + 4 * ch));
            } else {
                pk[j] = make_uint2(0, 0); pv[j] = make_uint2(0, 0); pcs[j] = make_uint2(0, 0);
            }
        }
    };

    if (beg < end) prefetch(beg);

    for (int p = beg; p < end; p++) {
        float4 ea = pea;
        uint2 ck[3], cv[3], ccs[3];
        #pragma unroll
        for (int j = 0; j < 3; j++) { ck[j] = pk[j]; cv[j] = pv[j]; ccs[j] = pcs[j]; }
        if (p + 1 < end) prefetch(p + 1);

        float4 k4[3], cs4[3], v4[3];
        #pragma unroll
        for (int j = 0; j < 3; j++) {
            k4[j] = h4tof4(ck[j]);
            v4[j] = h4tof4(cv[j]);
            cs4[j] = h4tof4(ccs[j]);
        }

        float l0 = 0, l1 = 0, l2 = 0, l3 = 0, l4 = 0;
        #pragma unroll
        for (int j = 0; j < 3; j++) {
            int ch = lane + 32 * j;
            if (ch >= 75) continue;
            int c = 4 * ch;
            #pragma unroll
            for (int i = 0; i < 4; i++) {
                int col = c + i;
                float h = fast_tanh((&cd[j].x)[i] + (&cs4[j].x)[i]
                                    + ea.z * sW2[col] + ea.w * sW2[DD + col]);
                const float* wc = sWcls + col * 5;
                l0 = fmaf(h, wc[0], l0); l1 = fmaf(h, wc[1], l1); l2 = fmaf(h, wc[2], l2);
                l3 = fmaf(h, wc[3], l3); l4 = fmaf(h, wc[4], l4);
            }
        }
        #pragma unroll
        for (int o = 16; o; o >>= 1) {
            l0 += __shfl_xor_sync(0xffffffffu, l0, o);
            l1 += __shfl_xor_sync(0xffffffffu, l1, o);
            l2 += __shfl_xor_sync(0xffffffffu, l2, o);
            l3 += __shfl_xor_sync(0xffffffffu, l3, o);
            l4 += __shfl_xor_sync(0xffffffffu, l4, o);
        }
        l0 += sBcls[0]; l1 += sBcls[1]; l2 += sBcls[2]; l3 += sBcls[3]; l4 += sBcls[4];
        float m = fmaxf(fmaxf(fmaxf(l0, l1), fmaxf(l2, l3)), l4);
        float p0 = __expf(l0 - m), p1 = __expf(l1 - m), p2 = __expf(l2 - m);
        float p3 = __expf(l3 - m), p4 = __expf(l4 - m);
        float inv = 1.0f / (p0 + p1 + p2 + p3 + p4);
        p0 *= inv; p1 *= inv; p2 *= inv; p3 *= inv; p4 *= inv;
        float t0 = ea.x > 0.0f ? 1.0f : 0.0f;
        float t1 = ea.y < 0.0f ? 1.0f : 0.0f;

        float4 ef[3];
        float a0 = 0, a1 = 0, a2 = 0, a3 = 0;
        #pragma unroll
        for (int j = 0; j < 3; j++) {
            int ch = lane + 32 * j;
            ef[j] = make_float4(0, 0, 0, 0);
            if (ch >= 75) continue;
            int c = 4 * ch;
            #pragma unroll
            for (int i = 0; i < 4; i++) {
                int col = c + i;
                float efv = sG[2100 + col];
                efv = fmaf(p0, sG[col], efv);
                efv = fmaf(p1, sG[300 + col], efv);
                efv = fmaf(p2, sG[600 + col], efv);
                efv = fmaf(p3, sG[900 + col], efv);
                efv = fmaf(p4, sG[1200 + col], efv);
                efv = fmaf(t0, sG[1500 + col], efv);
                efv = fmaf(t1, sG[1800 + col], efv);
                (&ef[j].x)[i] = efv;
                float pr = (&q[j].x)[i] * ((&k4[j].x)[i] + efv);
                if (col < 75) a0 += pr;
                else if (col < 150) a1 += pr;
                else if (col < 225) a2 += pr;
                else a3 += pr;
            }
        }
        #pragma unroll
        for (int o = 16; o; o >>= 1) {
            a0 += __shfl_xor_sync(0xffffffffu, a0, o);
            a1 += __shfl_xor_sync(0xffffffffu, a1, o);
            a2 += __shfl_xor_sync(0xffffffffu, a2, o);
            a3 += __shfl_xor_sync(0xffffffffu, a3, o);
        }
        const float sc = 0.115470053837925152f;  // 1/sqrt(75)
        float w0 = __expf(a0 * sc), w1 = __expf(a1 * sc);
        float w2 = __expf(a2 * sc), w3 = __expf(a3 * sc);
        den0 += w0; den1 += w1; den2 += w2; den3 += w3;

        #pragma unroll
        for (int j = 0; j < 3; j++) {
            int ch = lane + 32 * j;
            if (ch >= 75) continue;
            int c = 4 * ch;
            #pragma unroll
            for (int i = 0; i < 4; i++) {
                int col = c + i;
                float w = col < 75 ? w0 : (col < 150 ? w1 : (col < 225 ? w2 : w3));
                (&acc[j].x)[i] = fmaf(w, (&v4[j].x)[i] + (&ef[j].x)[i], (&acc[j].x)[i]);
            }
        }
    }

    float i0 = den0 > 0 ? __fdividef(1.0f, den0) : 0.0f;
    float i1 = den1 > 0 ? __fdividef(1.0f, den1) : 0.0f;
    float i2 = den2 > 0 ? __fdividef(1.0f, den2) : 0.0f;
    float i3 = den3 > 0 ? __fdividef(1.0f, den3) : 0.0f;
    #pragma unroll
    for (int j = 0; j < 3; j++) {
        int ch = lane + 32 * j;
        if (ch >= 75) continue;
        int c = 4 * ch;
        float4 o4 = *(float4*)&out[(size_t)n * DD + c];
        #pragma unroll
        for (int i = 0; i < 4; i++) {
            int col = c + i;
            float iv = col < 75 ? i0 : (col < 150 ? i1 : (col < 225 ? i2 : i3));
            (&o4.x)[i] = fmaf((&acc[j].x)[i], iv, (&o4.x)[i]);
        }
        *(float4*)&out[(size_t)n * DD + c] = o4;
    }
}

// ---------------- host launcher ----------------
extern "C" void kernel_launch(void* const* d_in, const int* in_sizes, int n_in,
                              void* d_out, int out_size) {
    const float* x     = (const float*)d_in[0];
    const int*   EI    = (const int*)d_in[1];
    const float* EA    = (const float*)d_in[2];
    const float* nrm   = (const float*)d_in[3];
    const float* Wq    = (const float*)d_in[4];
    const float* bq    = (const float*)d_in[5];
    const float* Wk    = (const float*)d_in[6];
    const float* bk    = (const float*)d_in[7];
    const float* Wv    = (const float*)d_in[8];
    const float* bv    = (const float*)d_in[9];
    const float* We    = (const float*)d_in[10];
    const float* Wn    = (const float*)d_in[11];
    const float* bn    = (const float*)d_in[12];
    const float* Wxy   = (const float*)d_in[13];
    const float* bxy   = (const float*)d_in[14];
    const float* Wloc  = (const float*)d_in[15];
    const float* bloc  = (const float*)d_in[16];
    const float* Wobj  = (const float*)d_in[17];
    const float* bobj  = (const float*)d_in[18];
    const float* Wfus  = (const float*)d_in[19];
    const float* bfus  = (const float*)d_in[20];
    const float* Wcls  = (const float*)d_in[21];
    const float* bcls  = (const float*)d_in[22];
    const float* Wskip = (const float*)d_in[23];
    const float* bskip = (const float*)d_in[24];
    const float* vocab = (const float*)d_in[25];

    int Nn = in_sizes[0] / DD;
    int Ee = in_sizes[1] / 2;
    float* out = (float*)d_out;

    static bool init_done = false;
    static cudaStream_t s2;
    static cudaEvent_t ev0, ev1;
    const int gemm_smem = STAGES * (128 * 40 + 128 * 40) * 2;   // 81920 B
    if (!init_done) {
        cudaFuncSetAttribute(gemm_fp16_kernel, cudaFuncAttributeMaxDynamicSharedMemorySize, gemm_smem);
        cudaStreamCreateWithFlags(&s2, cudaStreamNonBlocking);
        cudaEventCreateWithFlags(&ev0, cudaEventDisableTiming);
        cudaEventCreateWithFlags(&ev1, cudaEventDisableTiming);
        init_done = true;
    }

    // fork: CSR build + fold2 on side stream (independent of GEMM chain)
    cudaEventRecord(ev0, 0);
    cudaStreamWaitEvent(s2, ev0, 0);

    // main chain (GEMM is 4th launch on this stream for ncu capture)
    fold1_kernel<<<(DD + 127) / 128, 128>>>(Wn, Wxy, Wloc, Wfus, vocab, bxy, bn, bobj, bloc, bfus);
    buildA_kernel<<<(Nn * 304 + 255) / 256, 256>>>(x, nrm, Nn);
    buildW_kernel<<<(NCOLS * 304 + 255) / 256, 256>>>(Wq, Wk, Wv, Wskip, Wobj, bq, bk, bv, bskip);
    dim3 gg(15, MPAD / 128);
    gemm_fp16_kernel<<<gg, 256, gemm_smem>>>(out, Nn);
    fold2_kernel<<<(DD + 127) / 128, 128>>>(We);

    // side chain: CSR build
    int NB = (Nn + 255) / 256;
    zerodeg_kernel<<<NB, 256, 0, s2>>>(Nn);
    hist_kernel<<<(Ee + 255) / 256, 256, 0, s2>>>(EI, Ee);
    scan1_kernel<<<NB, 256, 0, s2>>>(Nn);
    scan2_kernel<<<1, 256, 0, s2>>>(NB);
    scan3_kernel<<<NB, 256, 0, s2>>>(Nn);
    scatter_kernel<<<(Ee + 255) / 256, 256, 0, s2>>>(EI, Ee);
    cudaEventRecord(ev1, s2);
    cudaStreamWaitEvent(0, ev1, 0);

    edgeF_kernel<<<(Nn + 7) / 8, 256>>>(EA, Wcls, bcls, out, Nn);
}